// round 11
// baseline (speedup 1.0000x reference)
#include <cuda_runtime.h>
#include <stdint.h>

#define BB 32
#define C  256
#define H  56
#define OH 28
#define HP 58
#define EPSV 1e-5f
#define NPIX (BB*OH*OH)     // 25088
#define NBLK (NPIX/128)     // 196

// ---------------- scratch ----------------
__device__ uint32_t g_x8u[BB*HP*HP*64];       // s8 sign(x), padded, channel-last
__device__ uint32_t g_w3f[72*16*32*4];        // frag-major W: [k32][mt16][lane32][4 u32]
__device__ uint32_t g_w1bits[2*C*8];          // 1x1 weight sign bits
__device__ float    g_pool[(size_t)NPIX*C];   // [pix][c]

// ---------------- s8 mma ----------------
__device__ __forceinline__ void mma_s8(int* c, const uint32_t* a, const uint32_t* b) {
    asm volatile(
        "mma.sync.aligned.m16n8k32.row.col.s32.s8.s8.s32 "
        "{%0,%1,%2,%3}, {%4,%5,%6,%7}, {%8,%9}, {%0,%1,%2,%3};"
        : "+r"(c[0]), "+r"(c[1]), "+r"(c[2]), "+r"(c[3])
        : "r"(a[0]), "r"(a[1]), "r"(a[2]), "r"(a[3]), "r"(b[0]), "r"(b[1]));
}
__device__ __forceinline__ void cpa16(uint32_t d, const void* s) {
    asm volatile("cp.async.cg.shared.global [%0], [%1], 16;" :: "r"(d), "l"(s));
}
#define CP_COMMIT() asm volatile("cp.async.commit_group;" ::: "memory")
#define CP_WAIT1()  asm volatile("cp.async.wait_group 1;" ::: "memory")
__device__ __forceinline__ uint32_t smem_u32(const void* p) {
    uint32_t a;
    asm("{ .reg .u64 t; cvta.to.shared.u64 t, %1; cvt.u32.u64 %0, t; }" : "=r"(a) : "l"(p));
    return a;
}

// ---------------- weight packing (frag-major W3 + bit-packed W1) ----------------
__global__ void pack_w(const float* __restrict__ w3, const float* __restrict__ w1) {
    int t = blockIdx.x*256 + threadIdx.x;
    if (t < 72*16*32*4) {
        int k32  = t >> 11;
        int rem  = t & 2047;
        int mt   = rem >> 7;
        int rem2 = rem & 127;
        int lane = rem2 >> 2;
        int r    = rem2 & 3;
        int g = lane >> 2, tg = lane & 3;
        int co  = mt*16 + g + (r & 1)*8;
        int tap = k32 >> 3, chq = k32 & 7;
        int chb = chq*32 + ((r >> 1) << 4) + tg*4;
        uint32_t pk = 0;
        #pragma unroll
        for (int z = 0; z < 4; z++) {
            float v = w3[((size_t)co*256 + chb + z)*9 + tap];
            int s = (v > 0.f) - (v < 0.f);
            pk |= ((uint32_t)(uint8_t)(int8_t)s) << (z*8);
        }
        g_w3f[t] = pk;
    } else if (t < 72*16*32*4 + 2*C*8) {
        int tt = t - 72*16*32*4;
        int co = tt >> 3, word = tt & 7;
        const float* p = w1 + (size_t)co*C + word*32;
        uint32_t bits = 0;
        #pragma unroll
        for (int j = 0; j < 32; j++)
            if (p[j] > 0.f) bits |= (1u << j);
        g_w1bits[tt] = bits;
    }
}

// ---------------- zero padded border of X8 ----------------
__global__ void border_zero() {
    int b = blockIdx.x, t = threadIdx.x;
    size_t base = (size_t)b*HP*HP*64;
    for (int i = t; i < HP*64; i += 256) {
        g_x8u[base + i] = 0;
        g_x8u[base + (size_t)(HP-1)*HP*64 + i] = 0;
    }
    for (int i = t; i < (HP-2)*64; i += 256) {
        int r = i >> 6, c = i & 63;
        g_x8u[base + (size_t)(r+1)*HP*64 + c] = 0;
        g_x8u[base + (size_t)(r+1)*HP*64 + (HP-1)*64 + c] = 0;
    }
}

// ---------------- fused s8-pack(sign(x)) + avgpool2x2 ----------------
__global__ void __launch_bounds__(256) packx8_pool(const float* __restrict__ x) {
    int tile = blockIdx.x;
    int i    = blockIdx.y;
    int b    = blockIdx.z;
    int tid = threadIdx.x, wid = tid >> 5, lane = tid & 31;

    __shared__ float    s_pool[7*256];
    __shared__ uint32_t s_s8[28*65];

    int r = lane / 14;
    int q = lane - r*14;
    bool active = (lane < 28);
    int rr = active ? r : 0;
    int row = 2*i + rr;
    int col = tile*14 + q;

    const float* xp = x + (((size_t)b*C + wid*32)*H + row)*H + col;

    uint32_t pk = 0;
    #pragma unroll
    for (int k = 0; k < 32; k++) {
        float v = active ? xp[(size_t)k*H*H] : 0.f;
        int s = (v > 0.f) - (v < 0.f);
        pk |= ((uint32_t)(uint8_t)(int8_t)s) << ((k & 3)*8);
        if ((k & 3) == 3) {
            if (active) s_s8[lane*65 + wid*8 + (k >> 2)] = pk;
            pk = 0;
        }
        float rs = v  + __shfl_down_sync(0xffffffffu, v, 14);
        float ps = rs + __shfl_down_sync(0xffffffffu, rs, 1);
        if (lane < 14 && (lane & 1) == 0)
            s_pool[(lane >> 1)*256 + wid*32 + k] = ps * 0.25f;
    }
    __syncthreads();

    for (int idx = tid; idx < 28*64; idx += 256) {
        int p = idx >> 6, c4 = idx & 63;
        int pr = p / 14, pq = p - pr*14;
        size_t rb = (((size_t)b*HP + (2*i + pr + 1))*HP + (tile*14 + pq + 1))*64;
        g_x8u[rb + c4] = s_s8[p*65 + c4];
    }
    for (int idx = tid; idx < 7*256; idx += 256) {
        int jl = idx >> 8, c = idx & 255;
        g_pool[ (((size_t)b*OH + i)*OH + tile*7 + jl)*C + c ] = s_pool[idx];
    }
}

// ---------------- IMMA conv3x3 + BN + pool + XNOR 1x1 + BN + concat ----------------
// Block = 128 pixels x 256 co, 512 threads (16 warps). Warp group (wid>>3)
// owns a 64-pixel half; per-group microkernel identical to the proven R9 one.
// Stage = half-tap (4 k32-steps): 18 stages, cp.async triple-buffered.
#define WBUF_SZ 32768                   // 4 k32-steps x [mt16][lane32][16B]
#define XSTRIDE 144
#define XBUF_SZ (128*XSTRIDE)           // 18432
#define BUF_SZ  (WBUF_SZ + XBUF_SZ)     // 51200
#define OFF_SHB (256*130*4)             // 133120 (dots/h region, stride 130)
#define SMEM_BYTES (3*BUF_SZ)           // 153600 (>= 133120+4608 epilogue)

__global__ void __launch_bounds__(512, 1) conv_mma(
    const float* __restrict__ g3, const float* __restrict__ b3,
    const float* __restrict__ m3, const float* __restrict__ v3,
    const float* __restrict__ g1, const float* __restrict__ b1,
    const float* __restrict__ m1, const float* __restrict__ v1,
    float* __restrict__ out)
{
    extern __shared__ __align__(16) char smem[];
    uint32_t sb = smem_u32(smem);
    int tid = threadIdx.x, wid = tid >> 5, lane = tid & 31;
    int g = lane >> 2, tg = lane & 3;
    int wg = wid >> 3;        // pixel half
    int wm = wid & 7;         // m-tile pair
    int p0 = blockIdx.x * 128;

    // staging geometry: thread t stages X pixel t>>2, two 16B chunks (t&3, +4)
    int pixrel = tid >> 2;
    int zi = tid & 3;
    int pixs = p0 + pixrel;
    int bbs = pixs / 784;
    int rms = pixs - bbs*784;
    int iis = rms / 28;
    int jjs = rms - iis*28;
    const char* xrow = (const char*)g_x8u + ((((size_t)bbs*HP + 2*iis)*HP + 2*jjs) << 8);

    int acc[2][8][4];
    #pragma unroll
    for (int m = 0; m < 2; m++)
        #pragma unroll
        for (int n = 0; n < 8; n++)
            #pragma unroll
            for (int k = 0; k < 4; k++) acc[m][n][k] = 0;

    // stage s = tap*2 + half: W 32KB (2048 chunks, 4/thread), X 128B/pix (2/thread)
    #define ISSUE(s) do { \
        int tap_ = (s) >> 1, half_ = (s) & 1; \
        int kh_ = tap_ / 3, kw_ = tap_ - kh_*3; \
        uint32_t bd = sb + ((s) % 3)*BUF_SZ; \
        const char* ws_ = (const char*)g_w3f + (size_t)(s)*32768; \
        cpa16(bd + (uint32_t)tid*16,          ws_ + (size_t)tid*16); \
        cpa16(bd + (uint32_t)(tid+512)*16,    ws_ + (size_t)(tid+512)*16); \
        cpa16(bd + (uint32_t)(tid+1024)*16,   ws_ + (size_t)(tid+1024)*16); \
        cpa16(bd + (uint32_t)(tid+1536)*16,   ws_ + (size_t)(tid+1536)*16); \
        const char* xs_ = xrow + (kh_*HP + kw_)*256 + half_*128; \
        cpa16(bd + WBUF_SZ + (uint32_t)pixrel*XSTRIDE + zi*16,        xs_ + zi*16); \
        cpa16(bd + WBUF_SZ + (uint32_t)pixrel*XSTRIDE + (zi+4)*16,    xs_ + (zi+4)*16); \
    } while (0)

    ISSUE(0); CP_COMMIT();
    ISSUE(1); CP_COMMIT();

    for (int s = 0; s < 18; s++) {
        CP_WAIT1();
        __syncthreads();
        if (s + 2 < 18) ISSUE(s + 2);
        CP_COMMIT();

        const char* Bf = smem + (s % 3)*BUF_SZ;
        const char* Xb = Bf + WBUF_SZ + wg*64*XSTRIDE;
        #pragma unroll
        for (int ks = 0; ks < 4; ks++) {
            uint32_t a[2][4], b[8][2];
            #pragma unroll
            for (int m = 0; m < 2; m++) {
                uint4 av = *(const uint4*)(Bf + ks*8192 + (wm*2 + m)*512 + lane*16);
                a[m][0] = av.x; a[m][1] = av.y; a[m][2] = av.z; a[m][3] = av.w;
            }
            #pragma unroll
            for (int n = 0; n < 8; n++) {
                const char* pb = Xb + (n*8 + g)*XSTRIDE + ks*32 + tg*4;
                b[n][0] = *(const uint32_t*)pb;
                b[n][1] = *(const uint32_t*)(pb + 16);
            }
            #pragma unroll
            for (int m = 0; m < 2; m++)
                #pragma unroll
                for (int n = 0; n < 8; n++)
                    mma_s8(acc[m][n], a[m], b[n]);
        }
    }
    __syncthreads();   // buffers dead; dots region reusable

    // ---- frag dump: acc -> s_dots[co][130] ----
    uint32_t* s_dots = (uint32_t*)smem;
    int m0 = wm*32;
    int pxb = wg*64;
    #pragma unroll
    for (int m = 0; m < 2; m++) {
        int co = m0 + m*16 + g;
        #pragma unroll
        for (int n = 0; n < 8; n++) {
            int px = pxb + n*8 + tg*2;
            *(uint2*)&s_dots[co*130 + px]     = make_uint2((uint32_t)acc[m][n][0], (uint32_t)acc[m][n][1]);
            *(uint2*)&s_dots[(co+8)*130 + px] = make_uint2((uint32_t)acc[m][n][2], (uint32_t)acc[m][n][3]);
        }
    }
    __syncthreads();

    // ---- pass2: BN3 + pool shortcut, h in place; sign bits ----
    float* s_hf = (float*)smem;
    uint32_t* s_hb = (uint32_t*)(smem + OFF_SHB);
    {
        int co = tid & 255;
        int pxg = (tid >> 8)*64;
        float inv = g3[co] * rsqrtf(v3[co] + EPSV);
        float add = b3[co] - m3[co]*inv;
        int wordi = co >> 5;
        #pragma unroll 4
        for (int k = 0; k < 64; k++) {
            int px = pxg + k;
            int dot = (int)s_dots[co*130 + px];
            float hv = (float)dot*inv + add + g_pool[(size_t)(p0 + px)*C + co];
            s_hf[co*130 + px] = hv;
            uint32_t mk = __ballot_sync(0xffffffffu, hv > 0.f);
            if (lane == 0) s_hb[px*9 + wordi] = mk;
        }
    }
    __syncthreads();

    // ---- phase C: XNOR 1x1 + BN + concat(h,h) ----
    uint32_t hb[4][8];
    #pragma unroll
    for (int pg = 0; pg < 4; pg++)
        #pragma unroll
        for (int w = 0; w < 8; w++)
            hb[pg][w] = s_hb[(pg*32 + lane)*9 + w];

    size_t ob[4];
    #pragma unroll
    for (int pg = 0; pg < 4; pg++) {
        int p = p0 + pg*32 + lane;
        int b2 = p / 784;
        int rm2 = p - b2*784;
        ob[pg] = (size_t)b2*512*784 + rm2;
    }

    const uint4* wtab = (const uint4*)g_w1bits;
    for (int co2 = wid; co2 < 512; co2 += 16) {
        uint4 w0  = __ldg(wtab + co2*2);
        uint4 w1q = __ldg(wtab + co2*2 + 1);
        float i1 = __ldg(g1 + co2) * rsqrtf(__ldg(v1 + co2) + EPSV);
        float a1 = __ldg(b1 + co2) - __ldg(m1 + co2)*i1;
        int hc = co2 & 255;
        #pragma unroll
        for (int pg = 0; pg < 4; pg++) {
            int P = 0;
            P += __popc(hb[pg][0] ^ w0.x);  P += __popc(hb[pg][1] ^ w0.y);
            P += __popc(hb[pg][2] ^ w0.z);  P += __popc(hb[pg][3] ^ w0.w);
            P += __popc(hb[pg][4] ^ w1q.x); P += __popc(hb[pg][5] ^ w1q.y);
            P += __popc(hb[pg][6] ^ w1q.z); P += __popc(hb[pg][7] ^ w1q.w);
            float hv = s_hf[hc*130 + pg*32 + lane];
            out[ob[pg] + (size_t)co2*784] = (float)(256 - 2*P)*i1 + a1 + hv;
        }
    }
}

// ---------------- launch ----------------
extern "C" void kernel_launch(void* const* d_in, const int* in_sizes, int n_in,
                              void* d_out, int out_size) {
    const float* x  = (const float*)d_in[0];
    const float* w3 = (const float*)d_in[1];
    const float* g3 = (const float*)d_in[2];
    const float* b3 = (const float*)d_in[3];
    const float* m3 = (const float*)d_in[4];
    const float* v3 = (const float*)d_in[5];
    const float* w1 = (const float*)d_in[6];
    const float* g1 = (const float*)d_in[7];
    const float* b1 = (const float*)d_in[8];
    const float* m1 = (const float*)d_in[9];
    const float* v1 = (const float*)d_in[10];
    float* out = (float*)d_out;

    cudaFuncSetAttribute(conv_mma, cudaFuncAttributeMaxDynamicSharedMemorySize, SMEM_BYTES);

    pack_w<<<(72*16*32*4 + 2*C*8 + 255)/256, 256>>>(w3, w1);
    border_zero<<<BB, 256>>>();
    packx8_pool<<<dim3(4, OH, BB), 256>>>(x);
    conv_mma<<<NBLK, 512, SMEM_BYTES>>>(g3, b3, m3, v3, g1, b1, m1, v1, out);
}